// round 3
// baseline (speedup 1.0000x reference)
#include <cuda_runtime.h>
#include <math.h>
#include <stdint.h>

#define BATCH   65536
#define IN_DIM  512
#define LATENT  32
#define NTRI    528
#define NPAD    544            // padded x row (544 % 32 == 0)
#define WENC_PAD 524           // conflict-free float4 weight rows
#define THREADS 256
#define WARPS   8
#define RPW     4
#define TILE_ROWS (WARPS*RPW)  // 32
#define NTILES  (BATCH/TILE_ROWS) // 2048
#define GRID    152

// ---- smem layout (floats) ----
#define OFF_WENC 0
#define SZ_WENC  (LATENT*WENC_PAD)              // 16768
#define OFF_WCH  (OFF_WENC + SZ_WENC)           // 16768  (interleaved col-pair layout, 544/row)
#define SZ_WCH   (LATENT*NPAD)                  // 17408
#define OFF_WMU  (OFF_WCH + SZ_WCH)             // 34176
#define OFF_BENC (OFF_WMU + LATENT*LATENT)      // 35200
#define OFF_BMU  (OFF_BENC + 32)                // 35232
#define OFF_BCH  (OFF_BMU + 32)                 // 35264 (544)
#define OFF_S    (OFF_BCH + NPAD)               // 35808
#define OFF_XBUF (OFF_S + 32)                   // 35840 (16B aligned)
#define WBUF_FLOATS (RPW*NPAD)                  // 2176 floats per warp (= 1088 u64: two 544-u64 L pair-bufs)
#define SMEM_FLOATS (OFF_XBUF + WARPS*WBUF_FLOATS) // 53248 floats = 212992 B

#define MU_OFF  ((size_t)BATCH*LATENT)
#define COV_OFF ((size_t)BATCH*LATENT*2)

#define LPAIR_U64 544          // padded-tri pair-buf size in u64

typedef unsigned long long ull;

__device__ __forceinline__ float lrelu(float v) { return v >= 0.f ? v : 0.01f * v; }

__device__ __forceinline__ ull pk2(float lo, float hi) {
    ull r; asm("mov.b64 %0, {%1,%2};" : "=l"(r) : "f"(lo), "f"(hi)); return r;
}
__device__ __forceinline__ float lo2(ull v) {
    float f; asm("{ .reg .f32 h; mov.b64 {%0, h}, %1; }" : "=f"(f) : "l"(v)); return f;
}
__device__ __forceinline__ float hi2(ull v) {
    float f; asm("{ .reg .f32 l; mov.b64 {l, %0}, %1; }" : "=f"(f) : "l"(v)); return f;
}
__device__ __forceinline__ ull fma2(ull a, ull b, ull c) {
    ull d; asm("fma.rn.f32x2 %0, %1, %2, %3;" : "=l"(d) : "l"(a), "l"(b), "l"(c)); return d;
}
// padded-triangular row offsets in u64 units: row i starts at tri(i) + ceil(i/2) (always even -> 16B aligned)
#define ROWOFF64(i) ((i)*((i)+1)/2 + (((i)+1)>>1))

__global__ void __launch_bounds__(THREADS)
pm_kernel(const float* __restrict__ x,       const float* __restrict__ W_enc,
          const float* __restrict__ b_enc,   const float* __restrict__ bn_gamma,
          const float* __restrict__ bn_beta, const float* __restrict__ bn_mean,
          const float* __restrict__ bn_var,  const float* __restrict__ W_mu,
          const float* __restrict__ b_mu,    const float* __restrict__ W_ch,
          const float* __restrict__ b_ch,    float* __restrict__ out)
{
    extern __shared__ float sm[];
    const int tid = threadIdx.x;

    // ---- stage + fold weights into smem ----
    if (tid < 32) {
        float s = bn_gamma[tid] * rsqrtf(bn_var[tid] + 1e-5f);
        sm[OFF_S + tid]    = s;
        sm[OFF_BENC + tid] = (b_enc[tid] - bn_mean[tid]) * s + bn_beta[tid];
        sm[OFF_BMU + tid]  = b_mu[tid];
    }
    __syncthreads();
    for (int idx = tid; idx < IN_DIM * LATENT; idx += THREADS) {
        int k = idx >> 5, j = idx & 31;
        sm[OFF_WENC + j * WENC_PAD + k] = W_enc[idx] * sm[OFF_S + j];  // transposed + BN fold
    }
    // W_ch: col-pair interleave. word w in row k:
    //   w < 512: cp = w>>6, lane = (w&63)>>1, s = w&1 -> col (2cp+s)*32+lane
    //   w >= 512: col = w  (512..527 real, rest zero)
    for (int idx = tid; idx < LATENT * NPAD; idx += THREADS) {
        int k = idx / NPAD, w = idx - k * NPAD;
        float v;
        if (w < 512) {
            int cp = w >> 6, ln = (w & 63) >> 1, s = w & 1;
            v = W_ch[k * NTRI + (2 * cp + s) * 32 + ln];
        } else {
            v = (w < NTRI) ? W_ch[k * NTRI + w] : 0.f;
        }
        sm[OFF_WCH + idx] = v;
    }
    for (int idx = tid; idx < LATENT * LATENT; idx += THREADS) sm[OFF_WMU + idx] = W_mu[idx];
    for (int idx = tid; idx < NPAD; idx += THREADS)            sm[OFF_BCH + idx] = (idx < NTRI) ? b_ch[idx] : 0.f;
    __syncthreads();

    const int warp = tid >> 5, lane = tid & 31;
    float* xw = sm + OFF_XBUF + warp * WBUF_FLOATS;   // x tile, later reused for L pair-bufs
    const float* wrow = sm + OFF_WENC + lane * WENC_PAD;

    for (int tile = blockIdx.x; tile < NTILES; tile += gridDim.x) {
        const int rbase = tile * TILE_ROWS + warp * RPW;

        // ---- load x[4][512] into per-warp smem (coalesced float4) ----
        #pragma unroll
        for (int r = 0; r < RPW; r++) {
            const float4* xg = (const float4*)(x + (size_t)(rbase + r) * IN_DIM);
            #pragma unroll
            for (int c = 0; c < 4; c++) {
                float4 v = xg[c * 32 + lane];
                *(float4*)(xw + r * NPAD + c * 128 + lane * 4) = v;
            }
        }
        __syncwarp();

        // ---- enc GEMM: h[r] for col=lane ----
        float h0 = 0.f, h1 = 0.f, h2 = 0.f, h3 = 0.f;
        #pragma unroll 4
        for (int k = 0; k < IN_DIM; k += 4) {
            float4 wv = *(const float4*)(wrow + k);
            float4 a0 = *(const float4*)(xw + 0 * NPAD + k);
            float4 a1 = *(const float4*)(xw + 1 * NPAD + k);
            float4 a2 = *(const float4*)(xw + 2 * NPAD + k);
            float4 a3 = *(const float4*)(xw + 3 * NPAD + k);
            h0 = fmaf(a0.x, wv.x, h0); h0 = fmaf(a0.y, wv.y, h0); h0 = fmaf(a0.z, wv.z, h0); h0 = fmaf(a0.w, wv.w, h0);
            h1 = fmaf(a1.x, wv.x, h1); h1 = fmaf(a1.y, wv.y, h1); h1 = fmaf(a1.z, wv.z, h1); h1 = fmaf(a1.w, wv.w, h1);
            h2 = fmaf(a2.x, wv.x, h2); h2 = fmaf(a2.y, wv.y, h2); h2 = fmaf(a2.z, wv.z, h2); h2 = fmaf(a2.w, wv.w, h2);
            h3 = fmaf(a3.x, wv.x, h3); h3 = fmaf(a3.y, wv.y, h3); h3 = fmaf(a3.z, wv.z, h3); h3 = fmaf(a3.w, wv.w, h3);
        }
        {
            float bj = sm[OFF_BENC + lane];
            h0 = lrelu(h0 + bj); h1 = lrelu(h1 + bj); h2 = lrelu(h2 + bj); h3 = lrelu(h3 + bj);
            out[(size_t)(rbase + 0) * 32 + lane] = h0;
            out[(size_t)(rbase + 1) * 32 + lane] = h1;
            out[(size_t)(rbase + 2) * 32 + lane] = h2;
            out[(size_t)(rbase + 3) * 32 + lane] = h3;
        }

        // ---- mu + ch GEMMs (f32x2, col-pair weights) ----
        ull acp[RPW][8];
        float ac16[RPW];
        ull amu01 = 0ull, amu23 = 0ull;
        #pragma unroll
        for (int r = 0; r < RPW; r++) {
            ac16[r] = 0.f;
            #pragma unroll
            for (int cp = 0; cp < 8; cp++) acp[r][cp] = 0ull;
        }

        #pragma unroll 2
        for (int k = 0; k < LATENT; k++) {
            float hv0 = __shfl_sync(0xffffffffu, h0, k);
            float hv1 = __shfl_sync(0xffffffffu, h1, k);
            float hv2 = __shfl_sync(0xffffffffu, h2, k);
            float hv3 = __shfl_sync(0xffffffffu, h3, k);
            // mu: rows packed, weight duplicated
            float wm = sm[OFF_WMU + k * 32 + lane];
            ull wmd  = pk2(wm, wm);
            amu01 = fma2(pk2(hv0, hv1), wmd, amu01);
            amu23 = fma2(pk2(hv2, hv3), wmd, amu23);
            // ch: col-pairs packed, h duplicated
            ull hd0 = pk2(hv0, hv0), hd1 = pk2(hv1, hv1), hd2 = pk2(hv2, hv2), hd3 = pk2(hv3, hv3);
            const ull* w2 = (const ull*)(sm + OFF_WCH + k * NPAD) + lane;
            #pragma unroll
            for (int cp = 0; cp < 8; cp++) {
                ull w = w2[cp * 32];
                acp[0][cp] = fma2(hd0, w, acp[0][cp]);
                acp[1][cp] = fma2(hd1, w, acp[1][cp]);
                acp[2][cp] = fma2(hd2, w, acp[2][cp]);
                acp[3][cp] = fma2(hd3, w, acp[3][cp]);
            }
            float wc16 = sm[OFF_WCH + k * NPAD + 512 + lane];
            ac16[0] = fmaf(hv0, wc16, ac16[0]);
            ac16[1] = fmaf(hv1, wc16, ac16[1]);
            ac16[2] = fmaf(hv2, wc16, ac16[2]);
            ac16[3] = fmaf(hv3, wc16, ac16[3]);
        }
        {
            float bm = sm[OFF_BMU + lane];
            out[MU_OFF + (size_t)(rbase + 0) * 32 + lane] = lrelu(lo2(amu01) + bm);
            out[MU_OFF + (size_t)(rbase + 1) * 32 + lane] = lrelu(hi2(amu01) + bm);
            out[MU_OFF + (size_t)(rbase + 2) * 32 + lane] = lrelu(lo2(amu23) + bm);
            out[MU_OFF + (size_t)(rbase + 3) * 32 + lane] = lrelu(hi2(amu23) + bm);
        }

        // ---- elts -> pair-interleaved padded-tri L (reuse x buffer) ----
        __syncwarp();   // x reads done
        ull* Lp0 = (ull*)xw;               // rows 0,1 packed   [0, 544)
        ull* Lp1 = (ull*)xw + LPAIR_U64;   // rows 2,3 packed   [544, 1088)
        #pragma unroll
        for (int c = 0; c < 17; c++) {
            int e = c * 32 + lane;
            if (c == 16 && e >= NTRI) continue;   // garbage tail of last chunk
            // e -> (i,j)
            int i = (int)((sqrtf(8.f * (float)e + 1.f) - 1.f) * 0.5f);
            int t = i * (i + 1) >> 1;
            if (e < t)               { i--; t -= i + 1; }
            else if (e >= t + i + 1) { t += i + 1; i++; }
            int off = (t + ((i + 1) >> 1)) + (e - t);   // ROWOFF64(i) + j
            float bc = sm[OFF_BCH + e];
            float v0, v1, v2, v3;
            if (c < 16) {
                ull p0 = acp[0][c >> 1], p1 = acp[1][c >> 1], p2 = acp[2][c >> 1], p3 = acp[3][c >> 1];
                if (c & 1) { v0 = hi2(p0); v1 = hi2(p1); v2 = hi2(p2); v3 = hi2(p3); }
                else       { v0 = lo2(p0); v1 = lo2(p1); v2 = lo2(p2); v3 = lo2(p3); }
            } else { v0 = ac16[0]; v1 = ac16[1]; v2 = ac16[2]; v3 = ac16[3]; }
            Lp0[off] = pk2(lrelu(v0 + bc), lrelu(v1 + bc));
            Lp1[off] = pk2(lrelu(v2 + bc), lrelu(v3 + bc));
        }
        // zero the pad element of odd-length rows (even i): 16 pads per pair-buf
        if (lane < 16) {
            int i = 2 * lane;
            int off = ROWOFF64(i) + i + 1;
            Lp0[off] = 0ull; Lp1[off] = 0ull;
        }
        __syncwarp();
        // diag transform (lane = L-row)
        {
            int off = ROWOFF64(lane) + lane;
            #pragma unroll
            for (int p = 0; p < 2; p++) {
                ull* Lp = p ? Lp1 : Lp0;
                ull v = Lp[off];
                float d0 = lo2(v), d1 = hi2(v);
                float s0 = (d0 > 20.f) ? d0 : log1pf(expf(d0));
                float s1 = (d1 > 20.f) ? d1 : log1pf(expf(d1));
                s0 = fminf(fmaxf(s0, 0.001f), 100.f) + 0.01f;
                s1 = fminf(fmaxf(s1, 0.001f), 100.f) + 0.01f;
                Lp[off] = pk2(s0, s1);
            }
        }
        __syncwarp();

        // ---- cov = L L^T + 0.01 I ; lane = output column k; 2 batch rows per pass ----
        const int klo = ROWOFF64(lane);
        #pragma unroll 1
        for (int p = 0; p < 2; p++) {
            const ull* Lp = p ? Lp1 : Lp0;
            ull Lk2[32];
            #pragma unroll
            for (int j = 0; j < 32; j++) {
                ull v = Lp[klo + j];
                Lk2[j] = (j <= lane) ? v : 0ull;
            }
            float* oc0 = out + COV_OFF + (size_t)(rbase + 2 * p)     * 1024;
            float* oc1 = out + COV_OFF + (size_t)(rbase + 2 * p + 1) * 1024;
            #pragma unroll
            for (int i = 0; i < 32; i++) {
                const int ro = ROWOFF64(i);
                const int E  = (i + 2) & ~1;          // padded element count (even)
                ull a0 = 0ull, a1 = 0ull;
                #pragma unroll
                for (int m = 0; m < E; m += 2) {
                    ulonglong2 lv = *(const ulonglong2*)(Lp + ro + m);  // row i, j=m..m+1 (pads are 0)
                    a0 = fma2(Lk2[m],     lv.x, a0);
                    a1 = fma2(Lk2[m + 1], lv.y, a1);
                }
                float c0 = lo2(a0) + lo2(a1);
                float c1 = hi2(a0) + hi2(a1);
                if (lane == i) { c0 += 0.01f; c1 += 0.01f; }
                oc0[i * 32 + lane] = c0;
                oc1[i * 32 + lane] = c1;
            }
        }
        __syncwarp();   // protect xw before next tile's x load
    }
}

extern "C" void kernel_launch(void* const* d_in, const int* in_sizes, int n_in,
                              void* d_out, int out_size)
{
    (void)in_sizes; (void)n_in; (void)out_size;
    const float* x        = (const float*)d_in[0];
    const float* W_enc    = (const float*)d_in[1];
    const float* b_enc    = (const float*)d_in[2];
    const float* bn_gamma = (const float*)d_in[3];
    const float* bn_beta  = (const float*)d_in[4];
    const float* bn_mean  = (const float*)d_in[5];
    const float* bn_var   = (const float*)d_in[6];
    const float* W_mu     = (const float*)d_in[7];
    const float* b_mu     = (const float*)d_in[8];
    const float* W_ch     = (const float*)d_in[9];
    const float* b_ch     = (const float*)d_in[10];
    float* out = (float*)d_out;

    cudaFuncSetAttribute(pm_kernel, cudaFuncAttributeMaxDynamicSharedMemorySize,
                         SMEM_FLOATS * (int)sizeof(float));
    pm_kernel<<<GRID, THREADS, SMEM_FLOATS * sizeof(float)>>>(
        x, W_enc, b_enc, bn_gamma, bn_beta, bn_mean, bn_var,
        W_mu, b_mu, W_ch, b_ch, out);
}

// round 4
// speedup vs baseline: 1.0002x; 1.0002x over previous
#include <cuda_runtime.h>
#include <math.h>
#include <stdint.h>

#define BATCH   65536
#define IN_DIM  512
#define LATENT  32
#define NTRI    528
#define NPAD    544            // padded x row (544 % 32 == 0)
#define WENC_PAD 524           // conflict-free float4 weight rows
#define THREADS 256
#define WARPS   8
#define RPW     4
#define TILE_ROWS (WARPS*RPW)  // 32
#define NTILES  (BATCH/TILE_ROWS) // 2048
#define GRID    152

// ---- smem layout (floats) ----
#define OFF_WENC 0
#define SZ_WENC  (LATENT*WENC_PAD)              // 16768
#define OFF_WCH  (OFF_WENC + SZ_WENC)           // 16768  (interleaved col-pair layout, 544/row)
#define SZ_WCH   (LATENT*NPAD)                  // 17408
#define OFF_WMU  (OFF_WCH + SZ_WCH)             // 34176
#define OFF_BENC (OFF_WMU + LATENT*LATENT)      // 35200
#define OFF_BMU  (OFF_BENC + 32)                // 35232
#define OFF_BCH  (OFF_BMU + 32)                 // 35264 (544)
#define OFF_S    (OFF_BCH + NPAD)               // 35808
#define OFF_XBUF (OFF_S + 32)                   // 35840 (16B aligned)
#define WBUF_FLOATS (RPW*NPAD)                  // 2176 floats per warp (= 1088 u64: two 544-u64 L pair-bufs)
#define SMEM_FLOATS (OFF_XBUF + WARPS*WBUF_FLOATS) // 53248 floats = 212992 B

#define MU_OFF  ((size_t)BATCH*LATENT)
#define COV_OFF ((size_t)BATCH*LATENT*2)

#define LPAIR_U64 544          // padded-tri pair-buf size in u64

typedef unsigned long long ull;

__device__ __forceinline__ float lrelu(float v) { return v >= 0.f ? v : 0.01f * v; }

__device__ __forceinline__ ull pk2(float lo, float hi) {
    ull r; asm("mov.b64 %0, {%1,%2};" : "=l"(r) : "f"(lo), "f"(hi)); return r;
}
__device__ __forceinline__ float lo2(ull v) {
    float f; asm("{ .reg .f32 h; mov.b64 {%0, h}, %1; }" : "=f"(f) : "l"(v)); return f;
}
__device__ __forceinline__ float hi2(ull v) {
    float f; asm("{ .reg .f32 l; mov.b64 {l, %0}, %1; }" : "=f"(f) : "l"(v)); return f;
}
__device__ __forceinline__ ull fma2(ull a, ull b, ull c) {
    ull d; asm("fma.rn.f32x2 %0, %1, %2, %3;" : "=l"(d) : "l"(a), "l"(b), "l"(c)); return d;
}
// padded-triangular row offsets in u64 units: row i starts at tri(i) + ceil(i/2) (always even -> 16B aligned)
#define ROWOFF64(i) ((i)*((i)+1)/2 + (((i)+1)>>1))

__global__ void __launch_bounds__(THREADS)
pm_kernel(const float* __restrict__ x,       const float* __restrict__ W_enc,
          const float* __restrict__ b_enc,   const float* __restrict__ bn_gamma,
          const float* __restrict__ bn_beta, const float* __restrict__ bn_mean,
          const float* __restrict__ bn_var,  const float* __restrict__ W_mu,
          const float* __restrict__ b_mu,    const float* __restrict__ W_ch,
          const float* __restrict__ b_ch,    float* __restrict__ out)
{
    extern __shared__ float sm[];
    const int tid = threadIdx.x;

    // ---- stage + fold weights into smem ----
    if (tid < 32) {
        float s = bn_gamma[tid] * rsqrtf(bn_var[tid] + 1e-5f);
        sm[OFF_S + tid]    = s;
        sm[OFF_BENC + tid] = (b_enc[tid] - bn_mean[tid]) * s + bn_beta[tid];
        sm[OFF_BMU + tid]  = b_mu[tid];
    }
    __syncthreads();
    for (int idx = tid; idx < IN_DIM * LATENT; idx += THREADS) {
        int k = idx >> 5, j = idx & 31;
        sm[OFF_WENC + j * WENC_PAD + k] = W_enc[idx] * sm[OFF_S + j];  // transposed + BN fold
    }
    // W_ch: col-pair interleave. word w in row k:
    //   w < 512: cp = w>>6, lane = (w&63)>>1, s = w&1 -> col (2cp+s)*32+lane
    //   w >= 512: col = w  (512..527 real, rest zero)
    for (int idx = tid; idx < LATENT * NPAD; idx += THREADS) {
        int k = idx / NPAD, w = idx - k * NPAD;
        float v;
        if (w < 512) {
            int cp = w >> 6, ln = (w & 63) >> 1, s = w & 1;
            v = W_ch[k * NTRI + (2 * cp + s) * 32 + ln];
        } else {
            v = (w < NTRI) ? W_ch[k * NTRI + w] : 0.f;
        }
        sm[OFF_WCH + idx] = v;
    }
    for (int idx = tid; idx < LATENT * LATENT; idx += THREADS) sm[OFF_WMU + idx] = W_mu[idx];
    for (int idx = tid; idx < NPAD; idx += THREADS)            sm[OFF_BCH + idx] = (idx < NTRI) ? b_ch[idx] : 0.f;
    __syncthreads();

    const int warp = tid >> 5, lane = tid & 31;
    float* xw = sm + OFF_XBUF + warp * WBUF_FLOATS;   // x tile, later reused for L pair-bufs
    const float* wrow = sm + OFF_WENC + lane * WENC_PAD;

    for (int tile = blockIdx.x; tile < NTILES; tile += gridDim.x) {
        const int rbase = tile * TILE_ROWS + warp * RPW;

        // ---- load x[4][512] into per-warp smem (coalesced float4) ----
        #pragma unroll
        for (int r = 0; r < RPW; r++) {
            const float4* xg = (const float4*)(x + (size_t)(rbase + r) * IN_DIM);
            #pragma unroll
            for (int c = 0; c < 4; c++) {
                float4 v = xg[c * 32 + lane];
                *(float4*)(xw + r * NPAD + c * 128 + lane * 4) = v;
            }
        }
        __syncwarp();

        // ---- enc GEMM: h[r] for col=lane ----
        float h0 = 0.f, h1 = 0.f, h2 = 0.f, h3 = 0.f;
        #pragma unroll 4
        for (int k = 0; k < IN_DIM; k += 4) {
            float4 wv = *(const float4*)(wrow + k);
            float4 a0 = *(const float4*)(xw + 0 * NPAD + k);
            float4 a1 = *(const float4*)(xw + 1 * NPAD + k);
            float4 a2 = *(const float4*)(xw + 2 * NPAD + k);
            float4 a3 = *(const float4*)(xw + 3 * NPAD + k);
            h0 = fmaf(a0.x, wv.x, h0); h0 = fmaf(a0.y, wv.y, h0); h0 = fmaf(a0.z, wv.z, h0); h0 = fmaf(a0.w, wv.w, h0);
            h1 = fmaf(a1.x, wv.x, h1); h1 = fmaf(a1.y, wv.y, h1); h1 = fmaf(a1.z, wv.z, h1); h1 = fmaf(a1.w, wv.w, h1);
            h2 = fmaf(a2.x, wv.x, h2); h2 = fmaf(a2.y, wv.y, h2); h2 = fmaf(a2.z, wv.z, h2); h2 = fmaf(a2.w, wv.w, h2);
            h3 = fmaf(a3.x, wv.x, h3); h3 = fmaf(a3.y, wv.y, h3); h3 = fmaf(a3.z, wv.z, h3); h3 = fmaf(a3.w, wv.w, h3);
        }
        {
            float bj = sm[OFF_BENC + lane];
            h0 = lrelu(h0 + bj); h1 = lrelu(h1 + bj); h2 = lrelu(h2 + bj); h3 = lrelu(h3 + bj);
            out[(size_t)(rbase + 0) * 32 + lane] = h0;
            out[(size_t)(rbase + 1) * 32 + lane] = h1;
            out[(size_t)(rbase + 2) * 32 + lane] = h2;
            out[(size_t)(rbase + 3) * 32 + lane] = h3;
        }

        // ---- mu + ch GEMMs (f32x2, col-pair weights) ----
        ull acp[RPW][8];
        float ac16[RPW];
        ull amu01 = 0ull, amu23 = 0ull;
        #pragma unroll
        for (int r = 0; r < RPW; r++) {
            ac16[r] = 0.f;
            #pragma unroll
            for (int cp = 0; cp < 8; cp++) acp[r][cp] = 0ull;
        }

        #pragma unroll 2
        for (int k = 0; k < LATENT; k++) {
            float hv0 = __shfl_sync(0xffffffffu, h0, k);
            float hv1 = __shfl_sync(0xffffffffu, h1, k);
            float hv2 = __shfl_sync(0xffffffffu, h2, k);
            float hv3 = __shfl_sync(0xffffffffu, h3, k);
            // mu: rows packed, weight duplicated
            float wm = sm[OFF_WMU + k * 32 + lane];
            ull wmd  = pk2(wm, wm);
            amu01 = fma2(pk2(hv0, hv1), wmd, amu01);
            amu23 = fma2(pk2(hv2, hv3), wmd, amu23);
            // ch: col-pairs packed, h duplicated
            ull hd0 = pk2(hv0, hv0), hd1 = pk2(hv1, hv1), hd2 = pk2(hv2, hv2), hd3 = pk2(hv3, hv3);
            const ull* w2 = (const ull*)(sm + OFF_WCH + k * NPAD) + lane;
            #pragma unroll
            for (int cp = 0; cp < 8; cp++) {
                ull w = w2[cp * 32];
                acp[0][cp] = fma2(hd0, w, acp[0][cp]);
                acp[1][cp] = fma2(hd1, w, acp[1][cp]);
                acp[2][cp] = fma2(hd2, w, acp[2][cp]);
                acp[3][cp] = fma2(hd3, w, acp[3][cp]);
            }
            float wc16 = sm[OFF_WCH + k * NPAD + 512 + lane];
            ac16[0] = fmaf(hv0, wc16, ac16[0]);
            ac16[1] = fmaf(hv1, wc16, ac16[1]);
            ac16[2] = fmaf(hv2, wc16, ac16[2]);
            ac16[3] = fmaf(hv3, wc16, ac16[3]);
        }
        {
            float bm = sm[OFF_BMU + lane];
            out[MU_OFF + (size_t)(rbase + 0) * 32 + lane] = lrelu(lo2(amu01) + bm);
            out[MU_OFF + (size_t)(rbase + 1) * 32 + lane] = lrelu(hi2(amu01) + bm);
            out[MU_OFF + (size_t)(rbase + 2) * 32 + lane] = lrelu(lo2(amu23) + bm);
            out[MU_OFF + (size_t)(rbase + 3) * 32 + lane] = lrelu(hi2(amu23) + bm);
        }

        // ---- elts -> pair-interleaved padded-tri L (reuse x buffer) ----
        __syncwarp();   // x reads done
        ull* Lp0 = (ull*)xw;               // rows 0,1 packed   [0, 544)
        ull* Lp1 = (ull*)xw + LPAIR_U64;   // rows 2,3 packed   [544, 1088)
        #pragma unroll
        for (int c = 0; c < 17; c++) {
            int e = c * 32 + lane;
            if (c == 16 && e >= NTRI) continue;   // garbage tail of last chunk
            // e -> (i,j)
            int i = (int)((sqrtf(8.f * (float)e + 1.f) - 1.f) * 0.5f);
            int t = i * (i + 1) >> 1;
            if (e < t)               { i--; t -= i + 1; }
            else if (e >= t + i + 1) { t += i + 1; i++; }
            int off = (t + ((i + 1) >> 1)) + (e - t);   // ROWOFF64(i) + j
            float bc = sm[OFF_BCH + e];
            float v0, v1, v2, v3;
            if (c < 16) {
                ull p0 = acp[0][c >> 1], p1 = acp[1][c >> 1], p2 = acp[2][c >> 1], p3 = acp[3][c >> 1];
                if (c & 1) { v0 = hi2(p0); v1 = hi2(p1); v2 = hi2(p2); v3 = hi2(p3); }
                else       { v0 = lo2(p0); v1 = lo2(p1); v2 = lo2(p2); v3 = lo2(p3); }
            } else { v0 = ac16[0]; v1 = ac16[1]; v2 = ac16[2]; v3 = ac16[3]; }
            Lp0[off] = pk2(lrelu(v0 + bc), lrelu(v1 + bc));
            Lp1[off] = pk2(lrelu(v2 + bc), lrelu(v3 + bc));
        }
        // zero the pad element of odd-length rows (even i): 16 pads per pair-buf
        if (lane < 16) {
            int i = 2 * lane;
            int off = ROWOFF64(i) + i + 1;
            Lp0[off] = 0ull; Lp1[off] = 0ull;
        }
        __syncwarp();
        // diag transform (lane = L-row)
        {
            int off = ROWOFF64(lane) + lane;
            #pragma unroll
            for (int p = 0; p < 2; p++) {
                ull* Lp = p ? Lp1 : Lp0;
                ull v = Lp[off];
                float d0 = lo2(v), d1 = hi2(v);
                float s0 = (d0 > 20.f) ? d0 : log1pf(expf(d0));
                float s1 = (d1 > 20.f) ? d1 : log1pf(expf(d1));
                s0 = fminf(fmaxf(s0, 0.001f), 100.f) + 0.01f;
                s1 = fminf(fmaxf(s1, 0.001f), 100.f) + 0.01f;
                Lp[off] = pk2(s0, s1);
            }
        }
        __syncwarp();

        // ---- cov = L L^T + 0.01 I ; lane = output column k; 2 batch rows per pass ----
        const int klo = ROWOFF64(lane);
        #pragma unroll 1
        for (int p = 0; p < 2; p++) {
            const ull* Lp = p ? Lp1 : Lp0;
            ull Lk2[32];
            #pragma unroll
            for (int j = 0; j < 32; j++) {
                ull v = Lp[klo + j];
                Lk2[j] = (j <= lane) ? v : 0ull;
            }
            float* oc0 = out + COV_OFF + (size_t)(rbase + 2 * p)     * 1024;
            float* oc1 = out + COV_OFF + (size_t)(rbase + 2 * p + 1) * 1024;
            #pragma unroll
            for (int i = 0; i < 32; i++) {
                const int ro = ROWOFF64(i);
                const int E  = (i + 2) & ~1;          // padded element count (even)
                ull a0 = 0ull, a1 = 0ull;
                #pragma unroll
                for (int m = 0; m < E; m += 2) {
                    ulonglong2 lv = *(const ulonglong2*)(Lp + ro + m);  // row i, j=m..m+1 (pads are 0)
                    a0 = fma2(Lk2[m],     lv.x, a0);
                    a1 = fma2(Lk2[m + 1], lv.y, a1);
                }
                float c0 = lo2(a0) + lo2(a1);
                float c1 = hi2(a0) + hi2(a1);
                if (lane == i) { c0 += 0.01f; c1 += 0.01f; }
                oc0[i * 32 + lane] = c0;
                oc1[i * 32 + lane] = c1;
            }
        }
        __syncwarp();   // protect xw before next tile's x load
    }
}

extern "C" void kernel_launch(void* const* d_in, const int* in_sizes, int n_in,
                              void* d_out, int out_size)
{
    (void)in_sizes; (void)n_in; (void)out_size;
    const float* x        = (const float*)d_in[0];
    const float* W_enc    = (const float*)d_in[1];
    const float* b_enc    = (const float*)d_in[2];
    const float* bn_gamma = (const float*)d_in[3];
    const float* bn_beta  = (const float*)d_in[4];
    const float* bn_mean  = (const float*)d_in[5];
    const float* bn_var   = (const float*)d_in[6];
    const float* W_mu     = (const float*)d_in[7];
    const float* b_mu     = (const float*)d_in[8];
    const float* W_ch     = (const float*)d_in[9];
    const float* b_ch     = (const float*)d_in[10];
    float* out = (float*)d_out;

    cudaFuncSetAttribute(pm_kernel, cudaFuncAttributeMaxDynamicSharedMemorySize,
                         SMEM_FLOATS * (int)sizeof(float));
    pm_kernel<<<GRID, THREADS, SMEM_FLOATS * sizeof(float)>>>(
        x, W_enc, b_enc, bn_gamma, bn_beta, bn_mean, bn_var,
        W_mu, b_mu, W_ch, b_ch, out);
}